// round 4
// baseline (speedup 1.0000x reference)
#include <cuda_runtime.h>
#include <cstdint>

// Problem constants
#define DIM    10
#define WIDTH  80
#define LEN_TH 971   // 10 + 10*80 + 80 + 80 + 1

#define OFF_BETA 0
#define OFF_A    10
#define OFF_B    810
#define OFF_C    890
#define OFF_D    970

#define WARPS_PER_BLOCK 8
#define NUM_BLOCKS      1184   // 148 SMs * 8 blocks/SM (31 regs -> 64 warps/SM fits)

// Persistent grid-stride: each warp loops over points with stride = total
// warps, so adjacent warps always process adjacent points (preserves L2
// boundary-sector sharing from the 12B-misaligned per-point theta bases).
// The loop lets the compiler overlap next-point loads with current-point
// tanh/reduction, removing per-CTA ramp gaps in DRAM demand.
__global__ __launch_bounds__(256) void u5_kernel(
    const float* __restrict__ theta,
    const float* __restrict__ x,
    float* __restrict__ out,
    int n_points)
{
    const int lane = threadIdx.x & 31;
    const int gwarp = blockIdx.x * WARPS_PER_BLOCK + (threadIdx.x >> 5);
    const int total_warps = NUM_BLOCKS * WARPS_PER_BLOCK;

    for (int p = gwarp; p < n_points; p += total_warps) {
        const float* __restrict__ th = theta + (size_t)p * LEN_TH;
        const float* __restrict__ xp = x + (size_t)p * DIM;

        // u0[d] = sin(pi * (x[d] - beta[d])), lanes 0..9 compute, broadcast
        float my_u0 = 0.0f;
        if (lane < DIM) {
            my_u0 = sinpif(__ldg(xp + lane) - __ldg(th + OFF_BETA + lane));
        }

        float u0[DIM];
#pragma unroll
        for (int d = 0; d < DIM; ++d) {
            u0[d] = __shfl_sync(0xffffffffu, my_u0, d);
        }

        // Each lane owns width columns: lane, lane+32, (lane<16) lane+64
        float acc0 = 0.0f, acc1 = 0.0f, acc2 = 0.0f;
        const float* __restrict__ A = th + OFF_A;
#pragma unroll
        for (int d = 0; d < DIM; ++d) {
            const float* __restrict__ row = A + d * WIDTH;
            acc0 = fmaf(u0[d], __ldg(row + lane),      acc0);
            acc1 = fmaf(u0[d], __ldg(row + lane + 32), acc1);
            if (lane < 16)
                acc2 = fmaf(u0[d], __ldg(row + lane + 64), acc2);
        }

        const float* __restrict__ B = th + OFF_B;
        const float* __restrict__ C = th + OFF_C;

        float h0 = tanhf(acc0 - __ldg(B + lane));
        float h1 = tanhf(acc1 - __ldg(B + lane + 32));
        float s  = h0 * __ldg(C + lane) + h1 * __ldg(C + lane + 32);
        if (lane < 16) {
            float h2 = tanhf(acc2 - __ldg(B + lane + 64));
            s = fmaf(h2, __ldg(C + lane + 64), s);
        }

        // Warp reduction
#pragma unroll
        for (int off = 16; off > 0; off >>= 1)
            s += __shfl_xor_sync(0xffffffffu, s, off);

        if (lane == 0)
            out[p] = s - __ldg(th + OFF_D);
    }
}

extern "C" void kernel_launch(void* const* d_in, const int* in_sizes, int n_in,
                              void* d_out, int out_size)
{
    const float* theta = (const float*)d_in[0];
    const float* x     = (const float*)d_in[1];
    float* out = (float*)d_out;

    const int n_points = out_size;   // 262144

    u5_kernel<<<NUM_BLOCKS, WARPS_PER_BLOCK * 32>>>(theta, x, out, n_points);
}

// round 5
// speedup vs baseline: 1.1722x; 1.1722x over previous
#include <cuda_runtime.h>
#include <cstdint>

// Problem constants
#define DIM    10
#define WIDTH  80
#define LEN_TH 971   // 10 + 10*80 + 80 + 80 + 1

// Offsets within a point's theta vector
#define OFF_BETA 0
#define OFF_A    10
#define OFF_B    810
#define OFF_C    890
#define OFF_D    970

#define WARPS_PER_BLOCK 4   // 128-thread CTAs: finer wave granularity than 256

// One warp per point. Identical inner computation to the 150us best kernel;
// only the CTA size changes (256 -> 128 threads) to smooth wave-boundary
// imbalance across the ~31 waves of this launch.
__global__ __launch_bounds__(128) void u5_kernel(
    const float* __restrict__ theta,
    const float* __restrict__ x,
    float* __restrict__ out,
    int n_points)
{
    const int warp_in_block = threadIdx.x >> 5;
    const int lane = threadIdx.x & 31;
    const int p = blockIdx.x * WARPS_PER_BLOCK + warp_in_block;
    if (p >= n_points) return;

    const float* __restrict__ th = theta + (size_t)p * LEN_TH;
    const float* __restrict__ xp = x + (size_t)p * DIM;

    // u0[d] = sin(pi * (x[d] - beta[d])), lanes 0..9 compute, broadcast
    float my_u0 = 0.0f;
    if (lane < DIM) {
        my_u0 = sinpif(xp[lane] - th[OFF_BETA + lane]);
    }

    float u0[DIM];
#pragma unroll
    for (int d = 0; d < DIM; ++d) {
        u0[d] = __shfl_sync(0xffffffffu, my_u0, d);
    }

    // Each lane accumulates width columns: lane, lane+32, and (lane<16) lane+64
    float acc0 = 0.0f, acc1 = 0.0f, acc2 = 0.0f;
    const float* __restrict__ A = th + OFF_A;
#pragma unroll
    for (int d = 0; d < DIM; ++d) {
        const float* __restrict__ row = A + d * WIDTH;
        acc0 = fmaf(u0[d], __ldg(row + lane), acc0);
        acc1 = fmaf(u0[d], __ldg(row + lane + 32), acc1);
        if (lane < 16)
            acc2 = fmaf(u0[d], __ldg(row + lane + 64), acc2);
    }

    const float* __restrict__ B = th + OFF_B;
    const float* __restrict__ C = th + OFF_C;

    float h0 = tanhf(acc0 - __ldg(B + lane));
    float h1 = tanhf(acc1 - __ldg(B + lane + 32));
    float s  = h0 * __ldg(C + lane) + h1 * __ldg(C + lane + 32);
    if (lane < 16) {
        float h2 = tanhf(acc2 - __ldg(B + lane + 64));
        s = fmaf(h2, __ldg(C + lane + 64), s);
    }

    // Warp reduction
#pragma unroll
    for (int off = 16; off > 0; off >>= 1)
        s += __shfl_xor_sync(0xffffffffu, s, off);

    if (lane == 0)
        out[p] = s - th[OFF_D];
}

extern "C" void kernel_launch(void* const* d_in, const int* in_sizes, int n_in,
                              void* d_out, int out_size)
{
    const float* theta = (const float*)d_in[0];
    const float* x     = (const float*)d_in[1];
    float* out = (float*)d_out;

    const int n_points = out_size;  // 262144
    const int blocks = (n_points + WARPS_PER_BLOCK - 1) / WARPS_PER_BLOCK;

    u5_kernel<<<blocks, WARPS_PER_BLOCK * 32>>>(theta, x, out, n_points);
}